// round 5
// baseline (speedup 1.0000x reference)
#include <cuda_runtime.h>
#include <cstdint>

#define Lq     8192
#define Eq     256
#define NCOL   2048      // 2 dirs * 4*HD
#define Tq     34
#define STARTq 32

// ---------------- scratch (static device globals; no runtime allocation) ----
__device__ float g_gates[Lq * NCOL];   // 64 MB: precomputed x@Wih^T + b, both dirs
__device__ float g_h[Lq * 512];        // 16 MB: [hf | hb]
__device__ float g_feats[Lq * Tq];
__device__ float g_la[Lq * Tq];
__device__ float g_lb[Lq * Tq];

// ============================================================================
// Phase A: embedding gather + input projection GEMM (unchanged, passing)
// ============================================================================
__global__ void xproj_kernel(const int* __restrict__ words,
                             const float* __restrict__ embed,
                             const float* __restrict__ Wf, const float* __restrict__ bf,
                             const float* __restrict__ Wb, const float* __restrict__ bb)
{
    __shared__ float As[32][64];
    __shared__ float Bs[32][64];
    __shared__ int   sw[64];

    const int tid = threadIdx.x;                 // 256 threads
    const int bn = blockIdx.x, bm = blockIdx.y;  // grid (32, 128)
    const int tx = tid & 15, ty = tid >> 4;      // 16x16

    if (tid < 64) sw[tid] = words[bm * 64 + tid];
    __syncthreads();

    float acc[4][4];
    #pragma unroll
    for (int i = 0; i < 4; i++)
        #pragma unroll
        for (int j = 0; j < 4; j++) acc[i][j] = 0.f;

    for (int k0 = 0; k0 < Eq; k0 += 32) {
        #pragma unroll
        for (int p = 0; p < 8; p++) {
            int lin = p * 256 + tid;
            int m = lin >> 5, kk = lin & 31;
            As[kk][m] = embed[(size_t)sw[m] * Eq + (k0 + kk)];
        }
        #pragma unroll
        for (int p = 0; p < 8; p++) {
            int lin = p * 256 + tid;
            int n = lin >> 5, kk = lin & 31;
            int col = bn * 64 + n;
            const float* W = (col < 1024) ? Wf : Wb;
            int row = (col < 1024) ? col : col - 1024;
            Bs[kk][n] = W[row * Eq + (k0 + kk)];
        }
        __syncthreads();
        #pragma unroll
        for (int kk = 0; kk < 32; kk++) {
            float4 av = *(const float4*)&As[kk][ty * 4];
            float4 bv = *(const float4*)&Bs[kk][tx * 4];
            float a[4] = {av.x, av.y, av.z, av.w};
            float b[4] = {bv.x, bv.y, bv.z, bv.w};
            #pragma unroll
            for (int i = 0; i < 4; i++)
                #pragma unroll
                for (int j = 0; j < 4; j++)
                    acc[i][j] = fmaf(a[i], b[j], acc[i][j]);
        }
        __syncthreads();
    }

    #pragma unroll
    for (int i = 0; i < 4; i++) {
        int t = bm * 64 + ty * 4 + i;
        #pragma unroll
        for (int j = 0; j < 4; j++) {
            int col = bn * 64 + tx * 4 + j;
            float bias = (col < 1024) ? bf[col] : bb[col - 1024];
            g_gates[(size_t)t * NCOL + col] = acc[i][j] + bias;
        }
    }
}

// ============================================================================
// Phase B: recurrent BiLSTM, restructured.
// Grid = 16 CTAs = 2 clusters of 8 (dir 0 fwd, 1 bwd). 512 threads/CTA.
// Thread role: unit j = tid>>4 (32 units/CTA), gate g = (tid>>2)&3, chunk c = tid&3.
// Per thread: 64-wide packed-f32x2 matvec chunk; shfl xor1/xor2 chunk reduce;
// activation; shfl xor4/xor8 gate gather; redundant cell update per 16 threads.
// h broadcast via st.async (1 store/thread) with mbarrier tx counting —
// no __syncthreads, no barrier.cluster in the loop.
// ============================================================================
__global__ void __cluster_dims__(8, 1, 1) __launch_bounds__(512, 1)
lstm_kernel(const float* __restrict__ Whh_f, const float* __restrict__ Whh_b)
{
    __shared__ __align__(16) float sh_h[2][256];
    __shared__ __align__(8)  unsigned long long sh_mbar[2];

    const int tid = threadIdx.x;
    unsigned rank; asm("mov.u32 %0, %%cluster_ctarank;" : "=r"(rank));
    const int dir = blockIdx.x >> 3;
    const int j   = tid >> 4;          // unit within CTA (0..31)
    const int g   = (tid >> 2) & 3;    // gate i,f,g,o
    const int c   = tid & 3;           // 64-col chunk
    const int u   = (int)rank * 32 + j;       // global hidden unit (0..255)
    const int row = g * 256 + u;              // Whh row
    const float* Whh = dir ? Whh_b : Whh_f;

    // weights: 64 floats packed as 32 f32x2 pairs in registers
    unsigned long long w2[32];
    {
        const ulonglong2* wp = (const ulonglong2*)(Whh + (size_t)row * 256 + c * 64);
        #pragma unroll
        for (int q = 0; q < 16; q++) { ulonglong2 t = wp[q]; w2[2*q] = t.x; w2[2*q+1] = t.y; }
    }

    const uint32_t hbase = (uint32_t)__cvta_generic_to_shared(&sh_h[0][0]);
    const uint32_t mbase = (uint32_t)__cvta_generic_to_shared(&sh_mbar[0]);

    if (tid < 256) sh_h[0][tid] = 0.f;
    if (tid == 0) {
        asm volatile("mbarrier.init.shared::cta.b64 [%0], 1;" :: "r"(mbase)     : "memory");
        asm volatile("mbarrier.init.shared::cta.b64 [%0], 1;" :: "r"(mbase + 8) : "memory");
        asm volatile("fence.mbarrier_init.release.cluster;" ::: "memory");
    }
    __syncthreads();
    asm volatile("barrier.cluster.arrive.aligned;" ::: "memory");
    asm volatile("barrier.cluster.wait.aligned;"   ::: "memory");

    // precomputed remote (mapa) addresses: data slot for both parities + both mbars
    uint32_t d0, d1, m0, m1;
    {
        int dst = tid & 7;
        uint32_t a0 = hbase + (uint32_t)(0 * 256 + u) * 4u;
        uint32_t a1 = hbase + (uint32_t)(1 * 256 + u) * 4u;
        asm("mapa.shared::cluster.u32 %0, %1, %2;" : "=r"(d0) : "r"(a0),        "r"(dst));
        asm("mapa.shared::cluster.u32 %0, %1, %2;" : "=r"(d1) : "r"(a1),        "r"(dst));
        asm("mapa.shared::cluster.u32 %0, %1, %2;" : "=r"(m0) : "r"(mbase),     "r"(dst));
        asm("mapa.shared::cluster.u32 %0, %1, %2;" : "=r"(m1) : "r"(mbase + 8u),"r"(dst));
    }

    const long xoff = (long)dir * 1024 + (long)g * 256 + u;
    float xc = g_gates[(long)(dir ? (Lq - 1) : 0) * NCOL + xoff];
    float cstate = 0.f;
    int ph0 = 0, ph1 = 0;

    for (int it = 0; it < Lq; ++it) {
        const int buf = it & 1, nb = buf ^ 1;
        const int tp  = dir ? (Lq - 1 - it) : it;

        if (it) {
            uint32_t mb = mbase + ((uint32_t)buf << 3);
            int p = buf ? ph1 : ph0;
            asm volatile("{\n\t.reg .pred P;\n\tWAIT%=:\n\t"
                "mbarrier.try_wait.parity.acquire.cluster.shared::cta.b64 P, [%0], %1;\n\t"
                "@!P bra WAIT%=;\n\t}" :: "r"(mb), "r"(p) : "memory");
            if (buf) ph1 ^= 1; else ph0 ^= 1;
        }
        if (tid == 0) {
            asm volatile("mbarrier.arrive.expect_tx.shared::cta.b64 _, [%0], %1;"
                         :: "r"(mbase + ((uint32_t)nb << 3)), "r"(1024) : "memory");
        }

        // prefetch next step's input-projection value
        float xn = 0.f;
        if (it + 1 < Lq) {
            int tpn = dir ? (Lq - 2 - it) : (it + 1);
            xn = g_gates[(long)tpn * NCOL + xoff];
        }

        // packed matvec: 64 MACs = 32 FFMA.f32x2
        unsigned long long acc0 = 0ull, acc1 = 0ull;
        uint32_t ha = hbase + (uint32_t)(buf * 1024 + c * 256);
        #pragma unroll
        for (int q = 0; q < 16; q++) {
            unsigned long long h0, h1;
            asm("ld.shared.v2.u64 {%0,%1}, [%2];" : "=l"(h0), "=l"(h1) : "r"(ha + q * 16));
            asm("fma.rn.f32x2 %0, %1, %2, %0;" : "+l"(acc0) : "l"(w2[2*q]),     "l"(h0));
            asm("fma.rn.f32x2 %0, %1, %2, %0;" : "+l"(acc1) : "l"(w2[2*q + 1]), "l"(h1));
        }
        float s;
        {
            float p0, p1, p2, p3;
            asm("mov.b64 {%0,%1}, %2;" : "=f"(p0), "=f"(p1) : "l"(acc0));
            asm("mov.b64 {%0,%1}, %2;" : "=f"(p2), "=f"(p3) : "l"(acc1));
            s = (p0 + p1) + (p2 + p3);
        }
        // chunk reduce (4 threads, same warp)
        s += __shfl_xor_sync(0xffffffffu, s, 1);
        s += __shfl_xor_sync(0xffffffffu, s, 2);
        float gv = s + xc;
        xc = xn;

        // activation (both paths, branchless select -> warp stays converged)
        float sig = __fdividef(1.f, 1.f + __expf(-gv));
        float th;  asm("tanh.approx.f32 %0, %1;" : "=f"(th) : "f"(gv));
        float av = (g == 2) ? th : sig;

        // gather all 4 gates of my unit (xor4 flips gate bit0, xor8 flips bit1)
        float u1 = __shfl_xor_sync(0xffffffffu, av, 4);   // gate g^1
        float u2 = __shfl_xor_sync(0xffffffffu, av, 8);   // gate g^2
        float u3 = __shfl_xor_sync(0xffffffffu, u1, 8);   // gate g^3

        float iv = (g == 0) ? av : (g == 1) ? u1 : (g == 2) ? u2 : u3;
        float fv = (g == 0) ? u1 : (g == 1) ? av : (g == 2) ? u3 : u2;
        float gg = (g == 0) ? u2 : (g == 1) ? u3 : (g == 2) ? av : u1;
        float ov = (g == 0) ? u3 : (g == 1) ? u2 : (g == 2) ? u1 : av;

        cstate = fmaf(fv, cstate, iv * gg);
        float cth; asm("tanh.approx.f32 %0, %1;" : "=f"(cth) : "f"(cstate));
        float hv = ov * cth;

        // broadcast h: one st.async per thread (8 of 16 threads/unit, dst=tid&7)
        if ((tid & 15) < 8) {
            uint32_t da = nb ? d1 : d0;
            uint32_t ma = nb ? m1 : m0;
            asm volatile("st.async.shared::cluster.mbarrier::complete_tx::bytes.b32 [%0], %1, [%2];"
                         :: "r"(da), "r"(__float_as_uint(hv)), "r"(ma) : "memory");
        } else if ((tid & 15) == 8) {
            g_h[(long)tp * 512 + dir * 256 + u] = hv;
        }
    }
    asm volatile("barrier.cluster.arrive.aligned;" ::: "memory");
    asm volatile("barrier.cluster.wait.aligned;"   ::: "memory");
}

// ============================================================================
// Phase C: feats[t][j] = h[t] . W_out[j] + b_out[j]   (unchanged, passing)
// ============================================================================
__global__ void feats_kernel(const float* __restrict__ Wout,
                             const float* __restrict__ bout)
{
    __shared__ float sh[4][512];
    const int tid = threadIdx.x;
    const int t0 = blockIdx.x * 4;
    #pragma unroll
    for (int p = 0; p < 8; p++) {
        int lin = p * 256 + tid;
        int r = lin >> 9, k = lin & 511;
        sh[r][k] = g_h[(long)(t0 + r) * 512 + k];
    }
    __syncthreads();
    const int tt = tid >> 6, j = tid & 63;
    if (j < Tq) {
        const float* wp = Wout + (size_t)j * 512;
        float s0 = 0.f, s1 = 0.f;
        #pragma unroll 8
        for (int k = 0; k < 512; k += 2) {
            s0 = fmaf(sh[tt][k],     __ldg(wp + k),     s0);
            s1 = fmaf(sh[tt][k + 1], __ldg(wp + k + 1), s1);
        }
        g_feats[(long)(t0 + tt) * Tq + j] = s0 + s1 + bout[j];
    }
}

// ============================================================================
// Phase D: CRF scans, lag-1-centered exp-domain recurrence.
// Store s_j = exp(score_j - prev_center); per step: dot, log, renorm by s0.
// One __syncthreads per step (double-buffered se), no max reduction.
// ============================================================================
__global__ void crf_kernel(const float* __restrict__ trans)
{
    __shared__ float se[2][Tq];
    const int j = threadIdx.x;         // 64 threads, j<34 active
    const bool act = (j < Tq);

    if (blockIdx.x == 0) {
        // ---------------- forward: alpha ----------------
        float er[Tq];
        float cc = 0.f;
        if (act) {
            #pragma unroll
            for (int i = 0; i < Tq; i++) er[i] = __expf(trans[j * Tq + i]);
            // t=0: alpha0 only finite at START -> a_j = trans[j][START] + feat0[j]
            float a = trans[j * Tq + STARTq] + g_feats[j];
            g_la[j] = a;
            se[0][j] = __expf(a);      // center c_{-1} = 0
        }
        __syncthreads();
        float fc = act ? g_feats[Tq + j] : 0.f;   // feat_1
        for (int t = 1; t < Lq; ++t) {
            const int rb = (t - 1) & 1, wb = t & 1;
            float fn = (act && t + 1 < Lq) ? g_feats[(long)(t + 1) * Tq + j] : 0.f;
            if (act) {
                float s0 = se[rb][0];
                float d0 = 0.f, d1 = 0.f;
                #pragma unroll
                for (int i = 0; i < Tq; i += 2) {
                    d0 = fmaf(er[i],     se[rb][i],     d0);
                    d1 = fmaf(er[i + 1], se[rb][i + 1], d1);
                }
                float dot = d0 + d1;
                float a = __logf(dot) + cc + fc;
                g_la[(long)t * Tq + j] = a;
                se[wb][j] = __fdividef(dot * __expf(fc), s0);
                cc += __logf(s0);
            }
            fc = fn;
            __syncthreads();
        }
    } else {
        // ---------------- backward: beta ----------------
        float ec[Tq];
        float cc = 0.f;
        if (act) {
            float ssum = 0.f;
            #pragma unroll
            for (int i = 0; i < Tq; i++) { ec[i] = __expf(trans[i * Tq + j]); ssum += ec[i]; }
            float b = __logf(ssum);                      // beta_{L-1}[j] = lse_i trans[i,j]
            g_lb[(long)(Lq - 1) * Tq + j] = b;
            se[0][j] = __expf(b + g_feats[(long)(Lq - 1) * Tq + j]);  // v = beta+feat, c=0
        }
        __syncthreads();
        float fc = act ? g_feats[(long)(Lq - 2) * Tq + j] : 0.f;
        int rb = 0;
        for (int t = Lq - 2; t >= 0; --t) {
            const int wb = rb ^ 1;
            float fn = (act && t > 0) ? g_feats[(long)(t - 1) * Tq + j] : 0.f;
            if (act) {
                float s0 = se[rb][0];
                float d0 = 0.f, d1 = 0.f;
                #pragma unroll
                for (int i = 0; i < Tq; i += 2) {
                    d0 = fmaf(ec[i],     se[rb][i],     d0);
                    d1 = fmaf(ec[i + 1], se[rb][i + 1], d1);
                }
                float dot = d0 + d1;
                float b = __logf(dot) + cc;              // beta_t[j]
                g_lb[(long)t * Tq + j] = b;
                se[wb][j] = __fdividef(dot * __expf(fc), s0);  // next v, lag-centered
                cc += __logf(s0);
            }
            fc = fn;
            rb ^= 1;
            __syncthreads();
        }
    }
}

// ============================================================================
// Phase E: score = la + lb ; tags = argmax(score)  (first max wins)
// ============================================================================
__global__ void final_kernel(float* __restrict__ out, int out_size)
{
    int t = blockIdx.x * blockDim.x + threadIdx.x;
    if (t >= Lq) return;
    float best = -3.4e38f;
    int bi = 0;
    #pragma unroll
    for (int j = 0; j < Tq; j++) {
        float s = g_la[(long)t * Tq + j] + g_lb[(long)t * Tq + j];
        out[(long)t * Tq + j] = s;
        if (s > best) { best = s; bi = j; }
    }
    if (out_size >= Lq * Tq + Lq) out[(long)Lq * Tq + t] = (float)bi;
}

// ============================================================================
extern "C" void kernel_launch(void* const* d_in, const int* in_sizes, int n_in,
                              void* d_out, int out_size)
{
    const int*   words = (const int*)  d_in[0];
    const float* embed = (const float*)d_in[1];
    const float* Wih_f = (const float*)d_in[2];
    const float* Whh_f = (const float*)d_in[3];
    const float* b_f   = (const float*)d_in[4];
    const float* Wih_b = (const float*)d_in[5];
    const float* Whh_b = (const float*)d_in[6];
    const float* b_b   = (const float*)d_in[7];
    const float* W_out = (const float*)d_in[8];
    const float* b_out = (const float*)d_in[9];
    const float* trans = (const float*)d_in[10];
    float* out = (float*)d_out;
    (void)Wih_f; (void)Wih_b;

    xproj_kernel<<<dim3(32, 128), 256>>>(words, embed, Wih_f, b_f, Wih_b, b_b);
    lstm_kernel<<<16, 512>>>(Whh_f, Whh_b);
    feats_kernel<<<Lq / 4, 256>>>(W_out, b_out);
    crf_kernel<<<2, 64>>>(trans);
    final_kernel<<<(Lq + 127) / 128, 128>>>(out, out_size);
}

// round 7
// speedup vs baseline: 1.0009x; 1.0009x over previous
#include <cuda_runtime.h>
#include <cstdint>

#define Lq     8192
#define Eq     256
#define NCOL   2048      // 2 dirs * 4*HD
#define Tq     34
#define STARTq 32

// ---------------- scratch (static device globals; no runtime allocation) ----
__device__ float g_gates[Lq * NCOL];   // 64 MB: precomputed x@Wih^T + b, both dirs
__device__ float g_h[Lq * 512];        // 16 MB: [hf | hb]
__device__ float g_feats[Lq * Tq];
__device__ float g_la[Lq * Tq];
__device__ float g_lb[Lq * Tq];

// ============================================================================
// Phase A: embedding gather + input projection GEMM (unchanged, passing)
// ============================================================================
__global__ void xproj_kernel(const int* __restrict__ words,
                             const float* __restrict__ embed,
                             const float* __restrict__ Wf, const float* __restrict__ bf,
                             const float* __restrict__ Wb, const float* __restrict__ bb)
{
    __shared__ float As[32][64];
    __shared__ float Bs[32][64];
    __shared__ int   sw[64];

    const int tid = threadIdx.x;                 // 256 threads
    const int bn = blockIdx.x, bm = blockIdx.y;  // grid (32, 128)
    const int tx = tid & 15, ty = tid >> 4;      // 16x16

    if (tid < 64) sw[tid] = words[bm * 64 + tid];
    __syncthreads();

    float acc[4][4];
    #pragma unroll
    for (int i = 0; i < 4; i++)
        #pragma unroll
        for (int j = 0; j < 4; j++) acc[i][j] = 0.f;

    for (int k0 = 0; k0 < Eq; k0 += 32) {
        #pragma unroll
        for (int p = 0; p < 8; p++) {
            int lin = p * 256 + tid;
            int m = lin >> 5, kk = lin & 31;
            As[kk][m] = embed[(size_t)sw[m] * Eq + (k0 + kk)];
        }
        #pragma unroll
        for (int p = 0; p < 8; p++) {
            int lin = p * 256 + tid;
            int n = lin >> 5, kk = lin & 31;
            int col = bn * 64 + n;
            const float* W = (col < 1024) ? Wf : Wb;
            int row = (col < 1024) ? col : col - 1024;
            Bs[kk][n] = W[row * Eq + (k0 + kk)];
        }
        __syncthreads();
        #pragma unroll
        for (int kk = 0; kk < 32; kk++) {
            float4 av = *(const float4*)&As[kk][ty * 4];
            float4 bv = *(const float4*)&Bs[kk][tx * 4];
            float a[4] = {av.x, av.y, av.z, av.w};
            float b[4] = {bv.x, bv.y, bv.z, bv.w};
            #pragma unroll
            for (int i = 0; i < 4; i++)
                #pragma unroll
                for (int j = 0; j < 4; j++)
                    acc[i][j] = fmaf(a[i], b[j], acc[i][j]);
        }
        __syncthreads();
    }

    #pragma unroll
    for (int i = 0; i < 4; i++) {
        int t = bm * 64 + ty * 4 + i;
        #pragma unroll
        for (int j = 0; j < 4; j++) {
            int col = bn * 64 + tx * 4 + j;
            float bias = (col < 1024) ? bf[col] : bb[col - 1024];
            g_gates[(size_t)t * NCOL + col] = acc[i][j] + bias;
        }
    }
}

// ============================================================================
// Phase B: recurrent BiLSTM.
// Grid = 16 CTAs = 2 clusters of 8 (dir 0 fwd, 1 bwd). 512 threads/CTA.
// Thread role: unit j = tid>>4, gate g = (tid>>2)&3, chunk c = tid&3.
// h broadcast via st.async + mbarrier tx counting; consumer uses
// HW-sleep relaxed.cta try_wait (60-cyc wakeup), no intra-loop CTA barriers.
// ============================================================================
__global__ void __cluster_dims__(8, 1, 1) __launch_bounds__(512, 1)
lstm_kernel(const float* __restrict__ Whh_f, const float* __restrict__ Whh_b)
{
    __shared__ __align__(16) float sh_h[2][256];
    __shared__ __align__(8)  unsigned long long sh_mbar[2];

    const int tid = threadIdx.x;
    unsigned rank; asm("mov.u32 %0, %%cluster_ctarank;" : "=r"(rank));
    const int dir = blockIdx.x >> 3;
    const int j   = tid >> 4;          // unit within CTA (0..31)
    const int g   = (tid >> 2) & 3;    // gate i,f,g,o
    const int c   = tid & 3;           // 64-col chunk
    const int u   = (int)rank * 32 + j;       // global hidden unit (0..255)
    const int row = g * 256 + u;              // Whh row
    const float* Whh = dir ? Whh_b : Whh_f;

    // weights: 64 floats packed as 32 f32x2 pairs in registers
    unsigned long long w2[32];
    {
        const ulonglong2* wp = (const ulonglong2*)(Whh + (size_t)row * 256 + c * 64);
        #pragma unroll
        for (int q = 0; q < 16; q++) { ulonglong2 t = wp[q]; w2[2*q] = t.x; w2[2*q+1] = t.y; }
    }

    const uint32_t hbase = (uint32_t)__cvta_generic_to_shared(&sh_h[0][0]);
    const uint32_t mbase = (uint32_t)__cvta_generic_to_shared(&sh_mbar[0]);

    if (tid < 256) sh_h[0][tid] = 0.f;
    if (tid == 0) {
        asm volatile("mbarrier.init.shared::cta.b64 [%0], 1;" :: "r"(mbase)     : "memory");
        asm volatile("mbarrier.init.shared::cta.b64 [%0], 1;" :: "r"(mbase + 8) : "memory");
        asm volatile("fence.mbarrier_init.release.cluster;" ::: "memory");
    }
    __syncthreads();
    asm volatile("barrier.cluster.arrive.aligned;" ::: "memory");
    asm volatile("barrier.cluster.wait.aligned;"   ::: "memory");

    // precomputed remote (mapa) addresses: data slot for both parities + both mbars
    uint32_t d0, d1, m0, m1;
    {
        int dst = tid & 7;
        uint32_t a0 = hbase + (uint32_t)(0 * 256 + u) * 4u;
        uint32_t a1 = hbase + (uint32_t)(1 * 256 + u) * 4u;
        asm("mapa.shared::cluster.u32 %0, %1, %2;" : "=r"(d0) : "r"(a0),        "r"(dst));
        asm("mapa.shared::cluster.u32 %0, %1, %2;" : "=r"(d1) : "r"(a1),        "r"(dst));
        asm("mapa.shared::cluster.u32 %0, %1, %2;" : "=r"(m0) : "r"(mbase),     "r"(dst));
        asm("mapa.shared::cluster.u32 %0, %1, %2;" : "=r"(m1) : "r"(mbase + 8u),"r"(dst));
    }

    const long xoff = (long)dir * 1024 + (long)g * 256 + u;
    float xc = g_gates[(long)(dir ? (Lq - 1) : 0) * NCOL + xoff];
    float cstate = 0.f;
    int ph0 = 0, ph1 = 0;

    for (int it = 0; it < Lq; ++it) {
        const int buf = it & 1, nb = buf ^ 1;
        const int tp  = dir ? (Lq - 1 - it) : it;

        if (it) {
            uint32_t mb = mbase + ((uint32_t)buf << 3);
            int p = buf ? ph1 : ph0;
            // HW-sleep wait: relaxed.cta try_wait with suspend-time hint.
            asm volatile("{\n\t.reg .pred P;\n\t"
                "WAIT%=:\n\t"
                "mbarrier.try_wait.parity.relaxed.cta.shared::cta.b64 P, [%0], %1, 0x989680;\n\t"
                "@P bra DONE%=;\n\t"
                "bra WAIT%=;\n\t"
                "DONE%=:\n\t}" :: "r"(mb), "r"(p) : "memory");
            if (buf) ph1 ^= 1; else ph0 ^= 1;
        }
        if (tid == 0) {
            asm volatile("mbarrier.arrive.expect_tx.shared::cta.b64 _, [%0], %1;"
                         :: "r"(mbase + ((uint32_t)nb << 3)), "r"(1024) : "memory");
        }

        // prefetch next step's input-projection value
        float xn = 0.f;
        if (it + 1 < Lq) {
            int tpn = dir ? (Lq - 2 - it) : (it + 1);
            xn = g_gates[(long)tpn * NCOL + xoff];
        }

        // packed matvec: 64 MACs = 32 FFMA.f32x2, 4 independent accumulators
        unsigned long long acc0 = 0ull, acc1 = 0ull, acc2 = 0ull, acc3 = 0ull;
        uint32_t ha = hbase + (uint32_t)(buf * 1024 + c * 256);
        #pragma unroll
        for (int q = 0; q < 8; q++) {
            unsigned long long h0, h1, h2, h3;
            asm("ld.shared.v2.u64 {%0,%1}, [%2];" : "=l"(h0), "=l"(h1) : "r"(ha + q * 32));
            asm("ld.shared.v2.u64 {%0,%1}, [%2];" : "=l"(h2), "=l"(h3) : "r"(ha + q * 32 + 16));
            asm("fma.rn.f32x2 %0, %1, %2, %0;" : "+l"(acc0) : "l"(w2[4*q + 0]), "l"(h0));
            asm("fma.rn.f32x2 %0, %1, %2, %0;" : "+l"(acc1) : "l"(w2[4*q + 1]), "l"(h1));
            asm("fma.rn.f32x2 %0, %1, %2, %0;" : "+l"(acc2) : "l"(w2[4*q + 2]), "l"(h2));
            asm("fma.rn.f32x2 %0, %1, %2, %0;" : "+l"(acc3) : "l"(w2[4*q + 3]), "l"(h3));
        }
        float s;
        {
            float p0, p1, p2, p3, p4, p5, p6, p7;
            asm("mov.b64 {%0,%1}, %2;" : "=f"(p0), "=f"(p1) : "l"(acc0));
            asm("mov.b64 {%0,%1}, %2;" : "=f"(p2), "=f"(p3) : "l"(acc1));
            asm("mov.b64 {%0,%1}, %2;" : "=f"(p4), "=f"(p5) : "l"(acc2));
            asm("mov.b64 {%0,%1}, %2;" : "=f"(p6), "=f"(p7) : "l"(acc3));
            s = ((p0 + p1) + (p2 + p3)) + ((p4 + p5) + (p6 + p7));
        }
        // chunk reduce (4 threads, same warp)
        s += __shfl_xor_sync(0xffffffffu, s, 1);
        s += __shfl_xor_sync(0xffffffffu, s, 2);
        float gv = s + xc;
        xc = xn;

        // activation: tanh gate directly; sigmoid via 0.5*tanh(x/2)+0.5
        float targ = (g == 2) ? gv : 0.5f * gv;
        float th;  asm("tanh.approx.f32 %0, %1;" : "=f"(th) : "f"(targ));
        float av = (g == 2) ? th : fmaf(0.5f, th, 0.5f);

        // gather all 4 gates of my unit (xor4 flips gate bit0, xor8 flips bit1)
        float u1 = __shfl_xor_sync(0xffffffffu, av, 4);   // gate g^1
        float u2 = __shfl_xor_sync(0xffffffffu, av, 8);   // gate g^2
        float u3 = __shfl_xor_sync(0xffffffffu, u1, 8);   // gate g^3

        float iv = (g == 0) ? av : (g == 1) ? u1 : (g == 2) ? u2 : u3;
        float fv = (g == 0) ? u1 : (g == 1) ? av : (g == 2) ? u3 : u2;
        float gg = (g == 0) ? u2 : (g == 1) ? u3 : (g == 2) ? av : u1;
        float ov = (g == 0) ? u3 : (g == 1) ? u2 : (g == 2) ? u1 : av;

        cstate = fmaf(fv, cstate, iv * gg);
        float cth; asm("tanh.approx.f32 %0, %1;" : "=f"(cth) : "f"(cstate));
        float hv = ov * cth;

        // broadcast h: one st.async per thread (8 of 16 threads/unit, dst=tid&7)
        if ((tid & 15) < 8) {
            uint32_t da = nb ? d1 : d0;
            uint32_t ma = nb ? m1 : m0;
            asm volatile("st.async.shared::cluster.mbarrier::complete_tx::bytes.b32 [%0], %1, [%2];"
                         :: "r"(da), "r"(__float_as_uint(hv)), "r"(ma) : "memory");
        } else if ((tid & 15) == 8) {
            g_h[(long)tp * 512 + dir * 256 + u] = hv;
        }
    }
    asm volatile("barrier.cluster.arrive.aligned;" ::: "memory");
    asm volatile("barrier.cluster.wait.aligned;"   ::: "memory");
}

// ============================================================================
// Phase C: feats[t][j] = h[t] . W_out[j] + b_out[j]   (unchanged, passing)
// ============================================================================
__global__ void feats_kernel(const float* __restrict__ Wout,
                             const float* __restrict__ bout)
{
    __shared__ float sh[4][512];
    const int tid = threadIdx.x;
    const int t0 = blockIdx.x * 4;
    #pragma unroll
    for (int p = 0; p < 8; p++) {
        int lin = p * 256 + tid;
        int r = lin >> 9, k = lin & 511;
        sh[r][k] = g_h[(long)(t0 + r) * 512 + k];
    }
    __syncthreads();
    const int tt = tid >> 6, j = tid & 63;
    if (j < Tq) {
        const float* wp = Wout + (size_t)j * 512;
        float s0 = 0.f, s1 = 0.f;
        #pragma unroll 8
        for (int k = 0; k < 512; k += 2) {
            s0 = fmaf(sh[tt][k],     __ldg(wp + k),     s0);
            s1 = fmaf(sh[tt][k + 1], __ldg(wp + k + 1), s1);
        }
        g_feats[(long)(t0 + tt) * Tq + j] = s0 + s1 + bout[j];
    }
}

// ============================================================================
// Phase D: CRF scans, lag-1-centered exp-domain recurrence (passing).
// ============================================================================
__global__ void crf_kernel(const float* __restrict__ trans)
{
    __shared__ float se[2][Tq];
    const int j = threadIdx.x;         // 64 threads, j<34 active
    const bool act = (j < Tq);

    if (blockIdx.x == 0) {
        // ---------------- forward: alpha ----------------
        float er[Tq];
        float cc = 0.f;
        if (act) {
            #pragma unroll
            for (int i = 0; i < Tq; i++) er[i] = __expf(trans[j * Tq + i]);
            float a = trans[j * Tq + STARTq] + g_feats[j];
            g_la[j] = a;
            se[0][j] = __expf(a);      // center c_{-1} = 0
        }
        __syncthreads();
        float fc = act ? g_feats[Tq + j] : 0.f;   // feat_1
        for (int t = 1; t < Lq; ++t) {
            const int rb = (t - 1) & 1, wb = t & 1;
            float fn = (act && t + 1 < Lq) ? g_feats[(long)(t + 1) * Tq + j] : 0.f;
            if (act) {
                float s0 = se[rb][0];
                float d0 = 0.f, d1 = 0.f;
                #pragma unroll
                for (int i = 0; i < Tq; i += 2) {
                    d0 = fmaf(er[i],     se[rb][i],     d0);
                    d1 = fmaf(er[i + 1], se[rb][i + 1], d1);
                }
                float dot = d0 + d1;
                float a = __logf(dot) + cc + fc;
                g_la[(long)t * Tq + j] = a;
                se[wb][j] = __fdividef(dot * __expf(fc), s0);
                cc += __logf(s0);
            }
            fc = fn;
            __syncthreads();
        }
    } else {
        // ---------------- backward: beta ----------------
        float ec[Tq];
        float cc = 0.f;
        if (act) {
            float ssum = 0.f;
            #pragma unroll
            for (int i = 0; i < Tq; i++) { ec[i] = __expf(trans[i * Tq + j]); ssum += ec[i]; }
            float b = __logf(ssum);                      // beta_{L-1}[j]
            g_lb[(long)(Lq - 1) * Tq + j] = b;
            se[0][j] = __expf(b + g_feats[(long)(Lq - 1) * Tq + j]);
        }
        __syncthreads();
        float fc = act ? g_feats[(long)(Lq - 2) * Tq + j] : 0.f;
        int rb = 0;
        for (int t = Lq - 2; t >= 0; --t) {
            const int wb = rb ^ 1;
            float fn = (act && t > 0) ? g_feats[(long)(t - 1) * Tq + j] : 0.f;
            if (act) {
                float s0 = se[rb][0];
                float d0 = 0.f, d1 = 0.f;
                #pragma unroll
                for (int i = 0; i < Tq; i += 2) {
                    d0 = fmaf(ec[i],     se[rb][i],     d0);
                    d1 = fmaf(ec[i + 1], se[rb][i + 1], d1);
                }
                float dot = d0 + d1;
                float b = __logf(dot) + cc;              // beta_t[j]
                g_lb[(long)t * Tq + j] = b;
                se[wb][j] = __fdividef(dot * __expf(fc), s0);
                cc += __logf(s0);
            }
            fc = fn;
            rb ^= 1;
            __syncthreads();
        }
    }
}

// ============================================================================
// Phase E: score = la + lb ; tags = argmax(score)  (first max wins)
// ============================================================================
__global__ void final_kernel(float* __restrict__ out, int out_size)
{
    int t = blockIdx.x * blockDim.x + threadIdx.x;
    if (t >= Lq) return;
    float best = -3.4e38f;
    int bi = 0;
    #pragma unroll
    for (int j = 0; j < Tq; j++) {
        float s = g_la[(long)t * Tq + j] + g_lb[(long)t * Tq + j];
        out[(long)t * Tq + j] = s;
        if (s > best) { best = s; bi = j; }
    }
    if (out_size >= Lq * Tq + Lq) out[(long)Lq * Tq + t] = (float)bi;
}

// ============================================================================
extern "C" void kernel_launch(void* const* d_in, const int* in_sizes, int n_in,
                              void* d_out, int out_size)
{
    const int*   words = (const int*)  d_in[0];
    const float* embed = (const float*)d_in[1];
    const float* Wih_f = (const float*)d_in[2];
    const float* Whh_f = (const float*)d_in[3];
    const float* b_f   = (const float*)d_in[4];
    const float* Wih_b = (const float*)d_in[5];
    const float* Whh_b = (const float*)d_in[6];
    const float* b_b   = (const float*)d_in[7];
    const float* W_out = (const float*)d_in[8];
    const float* b_out = (const float*)d_in[9];
    const float* trans = (const float*)d_in[10];
    float* out = (float*)d_out;

    xproj_kernel<<<dim3(32, 128), 256>>>(words, embed, Wih_f, b_f, Wih_b, b_b);
    lstm_kernel<<<16, 512>>>(Whh_f, Whh_b);
    feats_kernel<<<Lq / 4, 256>>>(W_out, b_out);
    crf_kernel<<<2, 64>>>(trans);
    final_kernel<<<(Lq + 127) / 128, 128>>>(out, out_size);
}